// round 7
// baseline (speedup 1.0000x reference)
#include <cuda_runtime.h>
#include <cstdint>

// ---------------- problem dims ----------------
#define MTOK 32768
#define DD   1024
#define NQKV 3072
#define NT   32            // K=1024 / BK=32 k-tiles

// ---------------- scratch (device globals; no allocation allowed) ----------------
__device__ float g_xr  [(size_t)MTOK * DD];      // tf32-rounded x
__device__ float g_wqkv[3 * DD * DD];            // packed wq|wk|wv (tf32)
__device__ float g_wor [DD * DD];                // tf32-rounded wo
__device__ float g_qkv [(size_t)MTOK * NQKV];    // packed q|k|v per token
__device__ float g_ctx [(size_t)MTOK * DD];      // tf32-rounded context

// ---------------- helpers ----------------
__device__ __forceinline__ float round_tf32(float x) {
    uint32_t r;
    asm("cvt.rna.tf32.f32 %0, %1;" : "=r"(r) : "f"(x));
    return __uint_as_float(r);
}

__global__ void round_x_kernel(float4* __restrict__ dst,
                               const float4* __restrict__ src, int n4) {
    int i = blockIdx.x * blockDim.x + threadIdx.x;
    if (i < n4) {
        float4 a = src[i];
        a.x = round_tf32(a.x); a.y = round_tf32(a.y);
        a.z = round_tf32(a.z); a.w = round_tf32(a.w);
        dst[i] = a;
    }
}

__global__ void round_wqkv_kernel(float4* __restrict__ dst,
                                  const float4* __restrict__ w0,
                                  const float4* __restrict__ w1,
                                  const float4* __restrict__ w2) {
    int i = blockIdx.x * blockDim.x + threadIdx.x;   // < 3*262144
    const float4* s = (i < 262144) ? w0 : (i < 524288 ? w1 : w2);
    float4 a = s[i & 262143];
    a.x = round_tf32(a.x); a.y = round_tf32(a.y);
    a.z = round_tf32(a.z); a.w = round_tf32(a.w);
    dst[i] = a;
}

// ---------------- TF32 GEMM (mma.sync): block tile 128(M) x 256(N), BK=32 ----------------
// 8 warps (2m x 4n), warp tile 64x64 (mf=4, nf=8). Padded smem rows (LDT=36),
// 3-stage cp.async ring, one CTA per SM.
#define LDT 36
#define A_TILE_F (128 * LDT)                 // 4608 floats (18432 B)
#define B_TILE_F (256 * LDT)                 // 9216 floats (36864 B)
#define STAGE_F  (A_TILE_F + B_TILE_F)       // 13824 floats
#define STAGE_BYTES (STAGE_F * 4)            // 55296 B

__device__ __forceinline__ void cp_async16(uint32_t smem, const void* gmem) {
    asm volatile("cp.async.cg.shared.global [%0], [%1], 16;\n" :: "r"(smem), "l"(gmem));
}

__global__ __launch_bounds__(256, 1)
void gemm_tf32(const float* __restrict__ A, const float* __restrict__ W,
               const float* __restrict__ b0, const float* __restrict__ b1,
               const float* __restrict__ b2, float* __restrict__ C, int ldc)
{
    extern __shared__ float sm[];
    uint32_t sm_u = (uint32_t)__cvta_generic_to_shared(sm);

    const int tid  = threadIdx.x;
    const int warp = tid >> 5, lane = tid & 31;
    const int wm   = warp >> 2, wn = warp & 3;     // 2(m) x 4(n)
    const int lt   = lane & 3,  lr = lane >> 2;
    const int K    = DD;

    // ---- loader state (fixed per thread) ----
    const int rowt = tid >> 3;                     // 0..31
    const int c4   = tid & 7;
    const float* aBase = A + (size_t)blockIdx.y * 128 * K + (size_t)rowt * K + c4 * 4;
    const float* bBase = W + (size_t)blockIdx.x * 256 * K + (size_t)rowt * K + c4 * 4;
    const uint32_t doff = (uint32_t)(rowt * 144 + c4 * 16);

    auto load_stage = [&](int kt, int s) {
        uint32_t st = sm_u + (uint32_t)s * STAGE_BYTES;
        const float* ap = aBase + kt * 32;
        const float* bp = bBase + kt * 32;
        #pragma unroll
        for (int i = 0; i < 4; i++)       // A: 128 rows
            cp_async16(st + doff + (uint32_t)i * 4608u, ap + (size_t)i * 32 * K);
        #pragma unroll
        for (int i = 0; i < 8; i++)       // B: 256 rows
            cp_async16(st + 18432u + doff + (uint32_t)i * 4608u, bp + (size_t)i * 32 * K);
        asm volatile("cp.async.commit_group;");
    };

    load_stage(0, 0);
    load_stage(1, 1);

    float acc[4][8][4];
    #pragma unroll
    for (int a = 0; a < 4; a++)
        #pragma unroll
        for (int b = 0; b < 8; b++)
            #pragma unroll
            for (int c = 0; c < 4; c++) acc[a][b][c] = 0.f;

    for (int kt = 0; kt < NT; kt++) {
        if (kt + 1 < NT) asm volatile("cp.async.wait_group 1;");
        else             asm volatile("cp.async.wait_group 0;");
        __syncthreads();
        if (kt + 2 < NT) load_stage(kt + 2, (kt + 2) % 3);

        const float* As = sm + (kt % 3) * STAGE_F;
        const float* Ws = As + A_TILE_F;

        #pragma unroll
        for (int kk = 0; kk < 4; kk++) {
            float af[4][4], bf[8][2];
            const int ar = wm * 64 + lr;
            const int ac = kk * 8 + lt;
            #pragma unroll
            for (int mf = 0; mf < 4; mf++) {
                af[mf][0] = As[(ar + mf * 16    ) * LDT + ac    ];
                af[mf][1] = As[(ar + mf * 16 + 8) * LDT + ac    ];
                af[mf][2] = As[(ar + mf * 16    ) * LDT + ac + 4];
                af[mf][3] = As[(ar + mf * 16 + 8) * LDT + ac + 4];
            }
            const int br = wn * 64 + lr;
            #pragma unroll
            for (int nf = 0; nf < 8; nf++) {
                bf[nf][0] = Ws[(br + nf * 8) * LDT + ac    ];
                bf[nf][1] = Ws[(br + nf * 8) * LDT + ac + 4];
            }
            #pragma unroll
            for (int mf = 0; mf < 4; mf++)
                #pragma unroll
                for (int nf = 0; nf < 8; nf++)
                    asm volatile(
                        "mma.sync.aligned.m16n8k8.row.col.f32.tf32.tf32.f32 "
                        "{%0,%1,%2,%3}, {%4,%5,%6,%7}, {%8,%9}, {%0,%1,%2,%3};"
                        : "+f"(acc[mf][nf][0]), "+f"(acc[mf][nf][1]),
                          "+f"(acc[mf][nf][2]), "+f"(acc[mf][nf][3])
                        : "r"(__float_as_uint(af[mf][0])), "r"(__float_as_uint(af[mf][1])),
                          "r"(__float_as_uint(af[mf][2])), "r"(__float_as_uint(af[mf][3])),
                          "r"(__float_as_uint(bf[nf][0])), "r"(__float_as_uint(bf[nf][1])));
        }
        __syncthreads();
    }

    // ---- epilogue: region-selected bias + float2 stores ----
    const int colbase = blockIdx.x * 256;
    const float* bias = (colbase < 1024) ? b0 : (colbase < 2048 ? b1 : b2);
    const int bofs    = colbase & 1023;
    const int crow0   = blockIdx.y * 128 + wm * 64 + lr;
    const int ccl     = wn * 64 + lt * 2;
    #pragma unroll
    for (int mf = 0; mf < 4; mf++) {
        #pragma unroll
        for (int nf = 0; nf < 8; nf++) {
            int r  = crow0 + mf * 16;
            int cl = ccl + nf * 8;
            float bb0 = __ldg(bias + bofs + cl), bb1 = __ldg(bias + bofs + cl + 1);
            *(float2*)&C[(size_t)r * ldc + colbase + cl] =
                make_float2(acc[mf][nf][0] + bb0, acc[mf][nf][1] + bb1);
            *(float2*)&C[(size_t)(r + 8) * ldc + colbase + cl] =
                make_float2(acc[mf][nf][2] + bb0, acc[mf][nf][3] + bb1);
        }
    }
}

// ---------------- per-token attention (softmax over HEAD axis) ----------------
__global__ void attn_kernel(const float* __restrict__ QKV, float* __restrict__ CTX)
{
    __shared__ float sq[16][68], sk[16][68], sv[16][68], sp[16][17];
    const int t   = blockIdx.x;
    const int tid = threadIdx.x;
    const int h   = tid >> 4;
    const int g   = tid & 15;

    const float4* r4 = (const float4*)(QKV + (size_t)t * NQKV);
    *(float4*)&sq[h][g * 4] = r4[tid];
    *(float4*)&sk[h][g * 4] = r4[256 + tid];
    *(float4*)&sv[h][g * 4] = r4[512 + tid];
    __syncthreads();

    float s = 0.f;
    #pragma unroll
    for (int d = 0; d < 16; d++) {
        float4 qa = *(const float4*)&sq[h][d * 4];
        float4 ka = *(const float4*)&sk[g][d * 4];
        s += qa.x * ka.x + qa.y * ka.y + qa.z * ka.z + qa.w * ka.w;
    }
    s *= 0.125f;

    float m = s;
    #pragma unroll
    for (int o = 8; o; o >>= 1) m = fmaxf(m, __shfl_xor_sync(0xffffffffu, m, o));
    float e = __expf(s - m);
    float sum = e;
    #pragma unroll
    for (int o = 8; o; o >>= 1) sum += __shfl_xor_sync(0xffffffffu, sum, o);
    sp[h][g] = e / sum;
    __syncthreads();

    float4 acc = make_float4(0.f, 0.f, 0.f, 0.f);
    #pragma unroll
    for (int gg = 0; gg < 16; gg++) {
        float p   = sp[h][gg];
        float4 va = *(const float4*)&sv[gg][g * 4];
        acc.x += p * va.x; acc.y += p * va.y;
        acc.z += p * va.z; acc.w += p * va.w;
    }
    acc.x = round_tf32(acc.x); acc.y = round_tf32(acc.y);
    acc.z = round_tf32(acc.z); acc.w = round_tf32(acc.w);
    ((float4*)(CTX + (size_t)t * DD))[tid] = acc;
}

// ---------------- launch (6 launches; #6 = O-GEMM for ncu -s5 -c1) ----------------
extern "C" void kernel_launch(void* const* d_in, const int* in_sizes, int n_in,
                              void* d_out, int out_size)
{
    const float* x  = (const float*)d_in[0];
    const float* wq = (const float*)d_in[1];
    const float* bq = (const float*)d_in[2];
    const float* wk = (const float*)d_in[3];
    const float* bk = (const float*)d_in[4];
    const float* wv = (const float*)d_in[5];
    const float* bv = (const float*)d_in[6];
    const float* wo = (const float*)d_in[7];
    const float* bo = (const float*)d_in[8];
    float* out = (float*)d_out;

    float *p_xr, *p_wqkv, *p_wor, *p_qkv, *p_ctx;
    cudaGetSymbolAddress((void**)&p_xr,   g_xr);
    cudaGetSymbolAddress((void**)&p_wqkv, g_wqkv);
    cudaGetSymbolAddress((void**)&p_wor,  g_wor);
    cudaGetSymbolAddress((void**)&p_qkv,  g_qkv);
    cudaGetSymbolAddress((void**)&p_ctx,  g_ctx);

    const int smem = 3 * STAGE_BYTES;   // 165888 B
    cudaFuncSetAttribute(gemm_tf32, cudaFuncAttributeMaxDynamicSharedMemorySize, smem);

    // 1) round x
    {
        int n4 = (int)((size_t)MTOK * DD / 4);
        round_x_kernel<<<(n4 + 255) / 256, 256>>>((float4*)p_xr, (const float4*)x, n4);
    }
    // 2) round+pack wq|wk|wv
    round_wqkv_kernel<<<(3 * 262144 + 255) / 256, 256>>>(
        (float4*)p_wqkv, (const float4*)wq, (const float4*)wk, (const float4*)wv);
    // 3) round wo
    {
        int w4 = DD * DD / 4;
        round_x_kernel<<<(w4 + 255) / 256, 256>>>((float4*)p_wor, (const float4*)wo, w4);
    }

    // 4) fused QKV projection: [32768,1024] @ [3072,1024]^T
    gemm_tf32<<<dim3(NQKV / 256, MTOK / 128), 256, smem>>>(
        p_xr, p_wqkv, bq, bk, bv, p_qkv, NQKV);

    // 5) per-token head-softmax attention
    attn_kernel<<<MTOK, 256>>>(p_qkv, p_ctx);

    // 6) output projection
    gemm_tf32<<<dim3(DD / 256, MTOK / 128), 256, smem>>>(
        p_ctx, p_wor, bo, bo, bo, out, DD);
}

// round 8
// speedup vs baseline: 2.0377x; 2.0377x over previous
#include <cuda_runtime.h>
#include <cuda_fp16.h>
#include <cstdint>

// ---------------- problem dims ----------------
#define MTOK 32768
#define DD   1024
#define NQKV 3072
#define NT   32            // K=1024 / BK=32 k-tiles

// ---------------- scratch (device globals) ----------------
__device__ __half g_xh   [(size_t)MTOK * DD];     // fp16 x
__device__ __half g_wqkvh[3 * DD * DD];           // packed wq|wk|wv fp16
__device__ __half g_woh  [DD * DD];               // fp16 wo
__device__ __half g_qkvh [(size_t)MTOK * NQKV];   // packed q|k|v fp16
__device__ __half g_ctxh [(size_t)MTOK * DD];     // fp16 context

// ---------------- helpers ----------------
__device__ __forceinline__ uint32_t pack_h2(float a, float b) {
    __half2 h = __floats2half2_rn(a, b);
    return *(uint32_t*)&h;
}

// fp32 -> fp16, 8 floats per thread
__global__ void f2h_kernel(uint4* __restrict__ dst, const float4* __restrict__ src, int n8) {
    int i = blockIdx.x * blockDim.x + threadIdx.x;
    if (i < n8) {
        float4 a = src[2 * i], b = src[2 * i + 1];
        uint4 o;
        o.x = pack_h2(a.x, a.y); o.y = pack_h2(a.z, a.w);
        o.z = pack_h2(b.x, b.y); o.w = pack_h2(b.z, b.w);
        dst[i] = o;
    }
}

// pack+convert wq|wk|wv (each 1024x1024 fp32)
__global__ void f2h3_kernel(uint4* __restrict__ dst, const float4* __restrict__ s0,
                            const float4* __restrict__ s1, const float4* __restrict__ s2) {
    int i = blockIdx.x * blockDim.x + threadIdx.x;   // < 3*131072
    const float4* s = (i < 131072) ? s0 : (i < 262144 ? s1 : s2);
    int j = (i & 131071) * 2;
    float4 a = s[j], b = s[j + 1];
    uint4 o;
    o.x = pack_h2(a.x, a.y); o.y = pack_h2(a.z, a.w);
    o.z = pack_h2(b.x, b.y); o.w = pack_h2(b.z, b.w);
    dst[i] = o;
}

// ---------------- fp16 GEMM: C[128,128] tile = A[M,K] @ W[N,K]^T + bias ----------------
// BK=32 halves (64B/row). Swizzled smem: 128B line = 2 tile rows; chunk' = sub ^ (line&7).
// 3-stage cp.async ring, 8 warps (2m x 4n), warp tile 64x32, mma m16n8k16, 2 CTA/SM.
#define STAGE_BYTES 16384    // A 8KB + B 8KB

__device__ __forceinline__ void cp_async16(uint32_t smem, const void* gmem) {
    asm volatile("cp.async.cg.shared.global [%0], [%1], 16;\n" :: "r"(smem), "l"(gmem));
}
__device__ __forceinline__ void ldsm4(uint32_t* r, uint32_t addr) {
    asm volatile("ldmatrix.sync.aligned.m8n8.x4.shared.b16 {%0,%1,%2,%3}, [%4];"
                 : "=r"(r[0]), "=r"(r[1]), "=r"(r[2]), "=r"(r[3]) : "r"(addr));
}

__global__ __launch_bounds__(256, 2)
void gemm_f16(const __half* __restrict__ A, const __half* __restrict__ W,
              const float* __restrict__ b0, const float* __restrict__ b1,
              const float* __restrict__ b2, float* __restrict__ Cf,
              __half* __restrict__ Ch, int ldc)
{
    extern __shared__ char smraw[];
    uint32_t sm_u = ((uint32_t)__cvta_generic_to_shared(smraw) + 1023u) & ~1023u;

    const int tid  = threadIdx.x;
    const int warp = tid >> 5, lane = tid & 31;
    const int wm   = warp >> 2, wn = warp & 3;     // 2(m) x 4(n)
    const int lt   = lane & 3,  lr = lane >> 2;
    const int K    = DD;

    // ---- loader: thread t handles A chunks (r=t>>2, c=t&3) and (r+64, c); same for B
    const int r0 = tid >> 2;
    const int c0 = tid & 3;
    const __half* aBase = A + (size_t)(blockIdx.y * 128 + r0) * K + c0 * 8;
    const __half* bBase = W + (size_t)(blockIdx.x * 128 + r0) * K + c0 * 8;
    const uint32_t lineL = (uint32_t)(r0 >> 1);
    const uint32_t subL  = (uint32_t)(((r0 & 1) << 2) | c0);
    const uint32_t doff  = lineL * 128u + ((subL ^ (lineL & 7u)) << 4);

    auto load_stage = [&](int kt, int s) {
        uint32_t st = sm_u + (uint32_t)s * STAGE_BYTES;
        const __half* ap = aBase + kt * 32;
        const __half* bp = bBase + kt * 32;
        cp_async16(st + doff,                  ap);
        cp_async16(st + doff + 4096u,          ap + (size_t)64 * K);
        cp_async16(st + 8192u + doff,          bp);
        cp_async16(st + 8192u + doff + 4096u,  bp + (size_t)64 * K);
        asm volatile("cp.async.commit_group;");
    };

    // ---- per-lane ldmatrix base offsets (kk=0, mf/pair=0)
    const int rlA  = (lane & 7) | (((lane >> 3) & 1) << 3);
    const int cA   = (lane >> 4) & 1;
    const int rowA = wm * 64 + rlA;
    const uint32_t lnA = (uint32_t)(rowA >> 1);
    const uint32_t sbA = (uint32_t)(((rlA & 1) << 2) | cA);
    const uint32_t offA = lnA * 128u + ((sbA ^ (lnA & 7u)) << 4);

    const int rlB  = (lane & 7) | (((lane >> 4) & 1) << 3);
    const int cB   = (lane >> 3) & 1;
    const int rowB = wn * 32 + rlB;
    const uint32_t lnB = (uint32_t)(rowB >> 1);
    const uint32_t sbB = (uint32_t)(((rlB & 1) << 2) | cB);
    const uint32_t offB = 8192u + lnB * 128u + ((sbB ^ (lnB & 7u)) << 4);

    load_stage(0, 0);
    load_stage(1, 1);

    float acc[4][4][4];
    #pragma unroll
    for (int a = 0; a < 4; a++)
        #pragma unroll
        for (int b = 0; b < 4; b++)
            #pragma unroll
            for (int c = 0; c < 4; c++) acc[a][b][c] = 0.f;

    for (int kt = 0; kt < NT; kt++) {
        if (kt + 1 < NT) asm volatile("cp.async.wait_group 1;");
        else             asm volatile("cp.async.wait_group 0;");
        __syncthreads();
        if (kt + 2 < NT) load_stage(kt + 2, (kt + 2) % 3);

        const uint32_t st = sm_u + (uint32_t)(kt % 3) * STAGE_BYTES;

        #pragma unroll
        for (int kk = 0; kk < 2; kk++) {
            const uint32_t ax = kk ? 32u : 0u;
            uint32_t a[4][4], b[2][4];
            #pragma unroll
            for (int mf = 0; mf < 4; mf++)
                ldsm4(a[mf], (st + offA + (uint32_t)mf * 1024u) ^ ax);
            #pragma unroll
            for (int pr = 0; pr < 2; pr++)
                ldsm4(b[pr], (st + offB + (uint32_t)pr * 1024u) ^ ax);

            #pragma unroll
            for (int mf = 0; mf < 4; mf++)
                #pragma unroll
                for (int nf = 0; nf < 4; nf++) {
                    const uint32_t bb0 = b[nf >> 1][(nf & 1) * 2];
                    const uint32_t bb1 = b[nf >> 1][(nf & 1) * 2 + 1];
                    asm volatile(
                        "mma.sync.aligned.m16n8k16.row.col.f32.f16.f16.f32 "
                        "{%0,%1,%2,%3}, {%4,%5,%6,%7}, {%8,%9}, {%0,%1,%2,%3};"
                        : "+f"(acc[mf][nf][0]), "+f"(acc[mf][nf][1]),
                          "+f"(acc[mf][nf][2]), "+f"(acc[mf][nf][3])
                        : "r"(a[mf][0]), "r"(a[mf][1]), "r"(a[mf][2]), "r"(a[mf][3]),
                          "r"(bb0), "r"(bb1));
                }
        }
        __syncthreads();
    }

    // ---- epilogue: region-selected bias; fp16 or fp32 output ----
    const int colbase = blockIdx.x * 128;
    const float* bias = (colbase < 1024) ? b0 : (colbase < 2048 ? b1 : b2);
    const int bofs    = colbase & 1023;
    const int crow0   = blockIdx.y * 128 + wm * 64 + lr;
    const int ccl     = wn * 32 + lt * 2;
    #pragma unroll
    for (int mf = 0; mf < 4; mf++) {
        #pragma unroll
        for (int nf = 0; nf < 4; nf++) {
            int r  = crow0 + mf * 16;
            int cl = ccl + nf * 8;
            float bb0 = __ldg(bias + bofs + cl), bb1 = __ldg(bias + bofs + cl + 1);
            float v00 = acc[mf][nf][0] + bb0, v01 = acc[mf][nf][1] + bb1;
            float v10 = acc[mf][nf][2] + bb0, v11 = acc[mf][nf][3] + bb1;
            if (Ch) {
                *(uint32_t*)&Ch[(size_t)r * ldc + colbase + cl]       = pack_h2(v00, v01);
                *(uint32_t*)&Ch[(size_t)(r + 8) * ldc + colbase + cl] = pack_h2(v10, v11);
            } else {
                *(float2*)&Cf[(size_t)r * ldc + colbase + cl]       = make_float2(v00, v01);
                *(float2*)&Cf[(size_t)(r + 8) * ldc + colbase + cl] = make_float2(v10, v11);
            }
        }
    }
}

// ---------------- per-token attention (softmax over HEAD axis), fp16 I/O ----------------
__global__ void attn_kernel(const __half* __restrict__ QKV, __half* __restrict__ CTX)
{
    __shared__ float sq[16][68], sk[16][68], sv[16][68], sp[16][17];
    const int t   = blockIdx.x;
    const int tid = threadIdx.x;
    const int h   = tid >> 4;
    const int g   = tid & 15;

    const uint2* r2 = (const uint2*)(QKV + (size_t)t * NQKV);   // 4 halves per uint2
    auto to4 = [](uint2 u, float* d) {
        __half2 h0 = *(__half2*)&u.x, h1 = *(__half2*)&u.y;
        float2 f0 = __half22float2(h0), f1 = __half22float2(h1);
        d[0] = f0.x; d[1] = f0.y; d[2] = f1.x; d[3] = f1.y;
    };
    float tmp[4];
    to4(r2[tid],       tmp); *(float4*)&sq[h][g * 4] = *(float4*)tmp;
    to4(r2[256 + tid], tmp); *(float4*)&sk[h][g * 4] = *(float4*)tmp;
    to4(r2[512 + tid], tmp); *(float4*)&sv[h][g * 4] = *(float4*)tmp;
    __syncthreads();

    float s = 0.f;
    #pragma unroll
    for (int d = 0; d < 16; d++) {
        float4 qa = *(const float4*)&sq[h][d * 4];
        float4 ka = *(const float4*)&sk[g][d * 4];
        s += qa.x * ka.x + qa.y * ka.y + qa.z * ka.z + qa.w * ka.w;
    }
    s *= 0.125f;

    float m = s;
    #pragma unroll
    for (int o = 8; o; o >>= 1) m = fmaxf(m, __shfl_xor_sync(0xffffffffu, m, o));
    float e = __expf(s - m);
    float sum = e;
    #pragma unroll
    for (int o = 8; o; o >>= 1) sum += __shfl_xor_sync(0xffffffffu, sum, o);
    sp[h][g] = e / sum;
    __syncthreads();

    float4 acc = make_float4(0.f, 0.f, 0.f, 0.f);
    #pragma unroll
    for (int gg = 0; gg < 16; gg++) {
        float p   = sp[h][gg];
        float4 va = *(const float4*)&sv[gg][g * 4];
        acc.x += p * va.x; acc.y += p * va.y;
        acc.z += p * va.z; acc.w += p * va.w;
    }
    uint2 o;
    o.x = pack_h2(acc.x, acc.y);
    o.y = pack_h2(acc.z, acc.w);
    ((uint2*)(CTX + (size_t)t * DD))[tid] = o;
}

// ---------------- launch (6 launches; #6 = O-GEMM for ncu -s5 -c1) ----------------
extern "C" void kernel_launch(void* const* d_in, const int* in_sizes, int n_in,
                              void* d_out, int out_size)
{
    const float* x  = (const float*)d_in[0];
    const float* wq = (const float*)d_in[1];
    const float* bq = (const float*)d_in[2];
    const float* wk = (const float*)d_in[3];
    const float* bk = (const float*)d_in[4];
    const float* wv = (const float*)d_in[5];
    const float* bv = (const float*)d_in[6];
    const float* wo = (const float*)d_in[7];
    const float* bo = (const float*)d_in[8];
    float* out = (float*)d_out;

    __half *p_xh, *p_wqkvh, *p_woh, *p_qkvh, *p_ctxh;
    cudaGetSymbolAddress((void**)&p_xh,    g_xh);
    cudaGetSymbolAddress((void**)&p_wqkvh, g_wqkvh);
    cudaGetSymbolAddress((void**)&p_woh,   g_woh);
    cudaGetSymbolAddress((void**)&p_qkvh,  g_qkvh);
    cudaGetSymbolAddress((void**)&p_ctxh,  g_ctxh);

    const int smem = 3 * STAGE_BYTES + 1024;   // 50176 B
    cudaFuncSetAttribute(gemm_f16, cudaFuncAttributeMaxDynamicSharedMemorySize, smem);

    // 1) x -> fp16
    {
        int n8 = (int)((size_t)MTOK * DD / 8);
        f2h_kernel<<<(n8 + 255) / 256, 256>>>((uint4*)p_xh, (const float4*)x, n8);
    }
    // 2) wq|wk|wv -> packed fp16
    f2h3_kernel<<<(3 * 131072 + 255) / 256, 256>>>(
        (uint4*)p_wqkvh, (const float4*)wq, (const float4*)wk, (const float4*)wv);
    // 3) wo -> fp16
    {
        int n8 = DD * DD / 8;
        f2h_kernel<<<(n8 + 255) / 256, 256>>>((uint4*)p_woh, (const float4*)wo, n8);
    }

    // 4) fused QKV projection: [32768,1024] @ [3072,1024]^T -> fp16
    gemm_f16<<<dim3(NQKV / 128, MTOK / 128), 256, smem>>>(
        p_xh, p_wqkvh, bq, bk, bv, nullptr, p_qkvh, NQKV);

    // 5) per-token head-softmax attention (fp16 in/out)
    attn_kernel<<<MTOK, 256>>>(p_qkvh, p_ctxh);

    // 6) output projection -> fp32 out
    gemm_f16<<<dim3(DD / 128, MTOK / 128), 256, smem>>>(
        p_ctxh, p_woh, bo, bo, bo, out, nullptr, DD);
}